// round 1
// baseline (speedup 1.0000x reference)
#include <cuda_runtime.h>
#include <math.h>

// SOFA attention, N=8192, x:[N,2] fp32 -> out:[N,2] fp32
//
// Math reduction:
//   l_i = |x_i|, ang_i = atan2(y,x)
//   mask_j = -1e9 if l_j < mean(l)+0.1*std(l, ddof=1) else 0
//   scores[i,j] = mask_j + 0.5*(l_i-l_j)^2 ; softmax over j ; out_ang = attn@ang
// Masked keys underflow to exactly 0 after max-subtraction (exp(-1e9+eps)==0 in fp32),
// so softmax runs over the compacted unmasked set only. The row max is analytic:
//   m_i = 0.5*max((l_i-Lmin_u)^2, (l_i-Lmax_u)^2)  over unmasked keys.

#define MAXN 16384

__device__ float g_l[MAXN];
__device__ float g_ang[MAXN];
__device__ float g_lu[MAXN];    // compacted unmasked lengths
__device__ float g_angu[MAXN];  // compacted unmasked angles
__device__ float g_thr;
__device__ int   g_cnt;
__device__ int   g_lmin_bits;   // float-as-int works: l >= 0
__device__ int   g_lmax_bits;

// ---------------- Kernel A: lengths + angles ----------------
__global__ void k_polar(const float* __restrict__ x, int n) {
    int i = blockIdx.x * blockDim.x + threadIdx.x;
    if (i < n) {
        float x0 = x[2 * i];
        float x1 = x[2 * i + 1];
        g_l[i]   = sqrtf(fmaf(x0, x0, x1 * x1));
        g_ang[i] = atan2f(x1, x0);
    }
}

// ---------------- Kernel B: deterministic mean/std + state reset ----------------
// Single block, fixed-order tree reduction -> bitwise-stable threshold per replay.
__global__ void k_stats(int n) {
    __shared__ float s1[1024];
    __shared__ float s2[1024];
    int t = threadIdx.x;
    float a = 0.f, b = 0.f;
    for (int i = t; i < n; i += 1024) {
        float l = g_l[i];
        a += l;
        b = fmaf(l, l, b);
    }
    s1[t] = a; s2[t] = b;
    __syncthreads();
    for (int off = 512; off; off >>= 1) {
        if (t < off) { s1[t] += s1[t + off]; s2[t] += s2[t + off]; }
        __syncthreads();
    }
    if (t == 0) {
        float sum = s1[0], sumsq = s2[0];
        float mean = sum / (float)n;
        float var  = (sumsq - sum * sum / (float)n) / (float)(n - 1);  // ddof=1
        g_thr = mean + 0.1f * sqrtf(var);
        g_cnt = 0;
        g_lmin_bits = 0x7f800000;  // +inf
        g_lmax_bits = 0;           // 0.0f
    }
}

// ---------------- Kernel C: compact unmasked keys + min/max ----------------
__global__ void k_compact(int n) {
    int i = blockIdx.x * blockDim.x + threadIdx.x;
    if (i < n) {
        float l = g_l[i];
        if (!(l < g_thr)) {  // unmasked
            int p = atomicAdd(&g_cnt, 1);
            g_lu[p]   = l;
            g_angu[p] = g_ang[i];
            atomicMin(&g_lmin_bits, __float_as_int(l));
            atomicMax(&g_lmax_bits, __float_as_int(l));
        }
    }
}

// ---------------- Kernel D: main attention loop ----------------
// 32 rows per block, SPLIT=8 key-splits per row -> 256 threads/block, 256 blocks.
#define ROWS_PB 32
#define SPLIT   8
__global__ void __launch_bounds__(ROWS_PB * SPLIT)
k_attn(float* __restrict__ out, int n) {
    int t   = threadIdx.x;
    int row = blockIdx.x * ROWS_PB + (t >> 3);
    int s   = t & (SPLIT - 1);
    if (row >= n) return;

    float li   = g_l[row];
    int   U    = g_cnt;
    float lmin = __int_as_float(g_lmin_bits);
    float lmax = __int_as_float(g_lmax_bits);
    float d0 = li - lmin, d1 = li - lmax;
    float m  = 0.5f * fmaxf(d0 * d0, d1 * d1);   // exact row max over unmasked keys

    float num = 0.f, den = 0.f;
    #pragma unroll 4
    for (int j = s; j < U; j += SPLIT) {
        float lj = __ldg(&g_lu[j]);
        float d  = li - lj;
        float e  = __expf(fmaf(0.5f * d, d, -m));   // exp(score - m), <= 1
        num = fmaf(e, __ldg(&g_angu[j]), num);
        den += e;
    }

    // reduce across the 8 key-splits of this row (lanes are group-aligned)
    #pragma unroll
    for (int off = SPLIT / 2; off; off >>= 1) {
        num += __shfl_down_sync(0xffffffffu, num, off, SPLIT);
        den += __shfl_down_sync(0xffffffffu, den, off, SPLIT);
    }

    if (s == 0) {
        float a = num / den;
        float sn, cs;
        sincosf(a, &sn, &cs);
        out[2 * row]     = li * cs;
        out[2 * row + 1] = li * sn;
    }
}

extern "C" void kernel_launch(void* const* d_in, const int* in_sizes, int n_in,
                              void* d_out, int out_size) {
    const float* x = (const float*)d_in[0];
    // d_in[1] = w, unused on the trainable=False path
    float* out = (float*)d_out;
    int n = in_sizes[0] / 2;

    k_polar<<<(n + 255) / 256, 256>>>(x, n);
    k_stats<<<1, 1024>>>(n);
    k_compact<<<(n + 255) / 256, 256>>>(n);
    k_attn<<<(n + ROWS_PB - 1) / ROWS_PB, ROWS_PB * SPLIT>>>(out, n);
}

// round 3
// speedup vs baseline: 1.7070x; 1.7070x over previous
#include <cuda_runtime.h>
#include <math.h>

// SOFA attention, N=8192, x:[N,2] fp32 -> out:[N,2] fp32
//
// Reductions:
//  - Masked keys (l_j < mean+0.1*std, ddof=1) contribute exactly 0 after softmax
//    (exp(-1e9+eps) flushes to 0 in fp32) -> compact to unmasked set U.
//  - softmax ratio is shift-invariant per row: exp(0.5(li-lj)^2) ratio equals
//    exp2(a_j + b_j*li) ratio with a_j = 0.5*lj^2*log2e, b_j = -lj*log2e
//    (row term 0.5*li^2 cancels; score spread <= ~6 nats -> no overflow).
//  - lane = row, warp streams keys -> broadcast 16B/key serves 32 pairs.

#define MAXN 16384
#define LOG2E 1.4426950408889634f
#define WARPS 8   // key-split warps per block
#define KCH   4   // key chunks across grid.y

__device__ float  g_l[MAXN];
__device__ float  g_ang[MAXN];
__device__ float4 g_keys[MAXN];        // (a_j, b_j, ang_j, pad)
__device__ float  g_thr;
__device__ int    g_cnt;
__device__ float  g_pnum[KCH * MAXN];  // per-chunk partials
__device__ float  g_pden[KCH * MAXN];

// ---------------- A: lengths + angles ----------------
__global__ void k_polar(const float* __restrict__ x, int n) {
    int i = blockIdx.x * blockDim.x + threadIdx.x;
    if (i < n) {
        float2 p = ((const float2*)x)[i];
        g_l[i]   = sqrtf(fmaf(p.x, p.x, p.y * p.y));
        g_ang[i] = atan2f(p.y, p.x);
    }
}

// ---------------- B: deterministic mean/std (ddof=1) ----------------
__global__ void k_stats(int n) {
    __shared__ float s1[1024];
    __shared__ float s2[1024];
    int t = threadIdx.x;
    float a = 0.f, b = 0.f;
    for (int i = t; i < n; i += 1024) {
        float l = g_l[i];
        a += l;
        b = fmaf(l, l, b);
    }
    s1[t] = a; s2[t] = b;
    __syncthreads();
    for (int off = 512; off; off >>= 1) {
        if (t < off) { s1[t] += s1[t + off]; s2[t] += s2[t + off]; }
        __syncthreads();
    }
    if (t == 0) {
        float sum = s1[0], sumsq = s2[0];
        float mean = sum / (float)n;
        float var  = (sumsq - sum * sum / (float)n) / (float)(n - 1);
        g_thr = mean + 0.1f * sqrtf(var);
        g_cnt = 0;
    }
}

// ---------------- C: compact unmasked keys, precompute (a,b,ang) ----------------
__global__ void k_compact(int n) {
    int i = blockIdx.x * blockDim.x + threadIdx.x;
    if (i < n) {
        float l = g_l[i];
        if (!(l < g_thr)) {
            int p = atomicAdd(&g_cnt, 1);
            g_keys[p] = make_float4(0.5f * l * l * LOG2E, -l * LOG2E, g_ang[i], 0.f);
        }
    }
}

__device__ __forceinline__ float ex2f(float t) {
    float e;
    asm("ex2.approx.f32 %0, %1;" : "=f"(e) : "f"(t));
    return e;
}

// ---------------- D: main loop. lane=row, warp streams a key chunk ----------------
__global__ void __launch_bounds__(32 * WARPS)
k_attn(int n) {
    __shared__ float2 s_red[WARPS][32];
    int lane = threadIdx.x & 31;
    int wid  = threadIdx.x >> 5;
    int row  = blockIdx.x * 32 + lane;
    int U    = g_cnt;
    int c0   = (int)(((long long)blockIdx.y * U) / KCH);
    int c1   = (int)(((long long)(blockIdx.y + 1) * U) / KCH);

    float li = (row < n) ? g_l[row] : 0.f;
    float num0 = 0.f, den0 = 0.f, num1 = 0.f, den1 = 0.f;

    int j = c0 + wid;
    #pragma unroll 2
    for (; j + WARPS < c1; j += 2 * WARPS) {
        float4 ka = __ldg(&g_keys[j]);             // uniform across warp -> broadcast
        float4 kb = __ldg(&g_keys[j + WARPS]);
        float ea = ex2f(fmaf(ka.y, li, ka.x));
        float eb = ex2f(fmaf(kb.y, li, kb.x));
        num0 = fmaf(ea, ka.z, num0);
        den0 += ea;
        num1 = fmaf(eb, kb.z, num1);
        den1 += eb;
    }
    if (j < c1) {
        float4 ka = __ldg(&g_keys[j]);
        float ea = ex2f(fmaf(ka.y, li, ka.x));
        num0 = fmaf(ea, ka.z, num0);
        den0 += ea;
    }
    float num = num0 + num1, den = den0 + den1;

    s_red[wid][lane] = make_float2(num, den);
    __syncthreads();
    if (wid == 0) {
        float sn = 0.f, sd = 0.f;
        #pragma unroll
        for (int w = 0; w < WARPS; w++) {
            float2 v = s_red[w][lane];
            sn += v.x; sd += v.y;
        }
        if (row < n) {
            g_pnum[blockIdx.y * MAXN + row] = sn;
            g_pden[blockIdx.y * MAXN + row] = sd;
        }
    }
}

// ---------------- E: combine chunks + epilogue ----------------
__global__ void k_fin(float* __restrict__ out, int n) {
    int i = blockIdx.x * blockDim.x + threadIdx.x;
    if (i < n) {
        float num = 0.f, den = 0.f;
        #pragma unroll
        for (int c = 0; c < KCH; c++) {
            num += g_pnum[c * MAXN + i];
            den += g_pden[c * MAXN + i];
        }
        float a = num / den;
        float sn, cs;
        sincosf(a, &sn, &cs);
        float li = g_l[i];
        ((float2*)out)[i] = make_float2(li * cs, li * sn);
    }
}

extern "C" void kernel_launch(void* const* d_in, const int* in_sizes, int n_in,
                              void* d_out, int out_size) {
    const float* x = (const float*)d_in[0];
    float* out = (float*)d_out;
    int n = in_sizes[0] / 2;

    k_polar<<<(n + 255) / 256, 256>>>(x, n);
    k_stats<<<1, 1024>>>(n);
    k_compact<<<(n + 255) / 256, 256>>>(n);
    dim3 grid((n + 31) / 32, KCH);
    k_attn<<<grid, 32 * WARPS>>>(n);
    k_fin<<<(n + 255) / 256, 256>>>(out, n);
}

// round 5
// speedup vs baseline: 1.7988x; 1.0538x over previous
#include <cuda_runtime.h>
#include <math.h>

// SOFA attention, N=8192, x:[N,2] fp32 -> out:[N,2] fp32
//
// Reductions:
//  - Masked keys (l_j < mean+0.1*std, ddof=1) contribute exactly 0 after softmax
//    (exp(-1e9+eps) flushes to 0 in fp32) -> compact to the unmasked set U.
//  - softmax ratio is shift-invariant per row: ratio of exp(0.5(li-lj)^2) equals
//    ratio of exp2(a_j + b_j*li), a_j = 0.5*lj^2*log2e, b_j = -lj*log2e
//    (row term cancels; |t| <= ~30 in log2 -> fp32 safe).
//  - KEY IDEA: out-angle a(l) = num(l)/den(l) depends on the row only through
//    the scalar l. Tabulate a(l) at M=2048 uniform points over [lmin, lmax]
//    (exact eval), then Catmull-Rom cubic per row. Error ~ h^4*|a''''|/384,
//    ~1e-10 with margin ~1e6 vs the 1e-3 gate. Cuts pairs & L1 traffic 4x.

#define MAXN  16384
#define M     2048
#define LOG2E 1.4426950408889634f
#define WARPS 8   // key-split warps per block (grid eval)
#define KC    4   // key chunks across grid.y

__device__ float  g_l[MAXN];
__device__ float  g_ang[MAXN];
__device__ float4 g_keys[MAXN];       // (a_j, b_j, ang_j, pad), index-ordered
__device__ int    g_cnt;
__device__ float  g_lo, g_h, g_invh;
__device__ float  g_pnum[KC * M];     // per-chunk partials at grid points
__device__ float  g_pden[KC * M];

// ---------------- A: lengths + angles ----------------
__global__ void k_polar(const float* __restrict__ x, int n) {
    int i = blockIdx.x * blockDim.x + threadIdx.x;
    if (i < n) {
        float2 p = ((const float2*)x)[i];
        g_l[i]   = sqrtf(fmaf(p.x, p.x, p.y * p.y));
        g_ang[i] = atan2f(p.y, p.x);
    }
}

// ---------------- B: stats (ddof=1) + min/max + deterministic compaction ----
// Single block, 1024 threads. Fixed-order reductions; prefix-scan compaction
// keeps keys in original index order -> bitwise-stable across replays.
__global__ void __launch_bounds__(1024)
k_statcompact(int n) {
    __shared__ float s1[1024], s2[1024], s3[1024], s4[1024];
    __shared__ int   wsum[32];
    __shared__ float sh_thr;
    int t = threadIdx.x;
    int lane = t & 31, wp = t >> 5;

    float a = 0.f, b = 0.f, mn = 1e30f, mx = -1e30f;
    for (int i = t; i < n; i += 1024) {
        float l = g_l[i];
        a += l;
        b = fmaf(l, l, b);
        mn = fminf(mn, l);
        mx = fmaxf(mx, l);
    }
    s1[t] = a; s2[t] = b; s3[t] = mn; s4[t] = mx;
    __syncthreads();
    for (int off = 512; off; off >>= 1) {
        if (t < off) {
            s1[t] += s1[t + off];
            s2[t] += s2[t + off];
            s3[t] = fminf(s3[t], s3[t + off]);
            s4[t] = fmaxf(s4[t], s4[t + off]);
        }
        __syncthreads();
    }
    if (t == 0) {
        float sum = s1[0], sumsq = s2[0];
        float mean = sum / (float)n;
        float var  = (sumsq - sum * sum / (float)n) / (float)(n - 1);
        sh_thr = mean + 0.1f * sqrtf(var);
        float lo = s3[0], hi = s4[0];
        float h  = (hi - lo) / (float)(M - 1);
        g_lo = lo; g_h = h; g_invh = 1.0f / h;
    }
    __syncthreads();
    float thr = sh_thr;

    // deterministic compaction: thread t owns contiguous range [t*per, ...)
    int per  = (n + 1023) >> 10;
    int base = t * per;
    int cnt  = 0;
    for (int k = 0; k < per; k++) {
        int i = base + k;
        if (i < n && !(g_l[i] < thr)) cnt++;
    }
    // block exclusive scan over 1024 counts
    int inc = cnt;
    #pragma unroll
    for (int o = 1; o < 32; o <<= 1) {
        int v = __shfl_up_sync(0xffffffffu, inc, o);
        if (lane >= o) inc += v;
    }
    if (lane == 31) wsum[wp] = inc;
    __syncthreads();
    if (wp == 0) {
        int v = wsum[lane];
        #pragma unroll
        for (int o = 1; o < 32; o <<= 1) {
            int u = __shfl_up_sync(0xffffffffu, v, o);
            if (lane >= o) v += u;
        }
        wsum[lane] = v;
    }
    __syncthreads();
    int p = inc - cnt + (wp > 0 ? wsum[wp - 1] : 0);
    for (int k = 0; k < per; k++) {
        int i = base + k;
        if (i < n) {
            float l = g_l[i];
            if (!(l < thr)) {
                g_keys[p] = make_float4(0.5f * l * l * LOG2E, -l * LOG2E, g_ang[i], 0.f);
                p++;
            }
        }
    }
    if (t == 1023) g_cnt = wsum[31];
}

__device__ __forceinline__ float ex2f(float t) {
    float e;
    asm("ex2.approx.f32 %0, %1;" : "=f"(e) : "f"(t));
    return e;
}

// ---------------- C: tabulate num/den at M grid points ----------------
// lane = grid point (32 per block), 8 warps x KC chunks split the keys.
__global__ void __launch_bounds__(32 * WARPS)
k_grid() {
    __shared__ float2 s_red[WARPS][32];
    int lane = threadIdx.x & 31;
    int wid  = threadIdx.x >> 5;
    int gpt  = blockIdx.x * 32 + lane;
    int U    = g_cnt;
    int c0   = (int)(((long long)blockIdx.y * U) / KC);
    int c1   = (int)(((long long)(blockIdx.y + 1) * U) / KC);

    float lg = fmaf((float)gpt, g_h, g_lo);
    float num0 = 0.f, den0 = 0.f, num1 = 0.f, den1 = 0.f;

    int j = c0 + wid;
    #pragma unroll 2
    for (; j + WARPS < c1; j += 2 * WARPS) {
        float4 ka = __ldg(&g_keys[j]);             // uniform -> broadcast
        float4 kb = __ldg(&g_keys[j + WARPS]);
        float ea = ex2f(fmaf(ka.y, lg, ka.x));
        float eb = ex2f(fmaf(kb.y, lg, kb.x));
        num0 = fmaf(ea, ka.z, num0);
        den0 += ea;
        num1 = fmaf(eb, kb.z, num1);
        den1 += eb;
    }
    if (j < c1) {
        float4 ka = __ldg(&g_keys[j]);
        float ea = ex2f(fmaf(ka.y, lg, ka.x));
        num0 = fmaf(ea, ka.z, num0);
        den0 += ea;
    }

    s_red[wid][lane] = make_float2(num0 + num1, den0 + den1);
    __syncthreads();
    if (wid == 0) {
        float sn = 0.f, sd = 0.f;
        #pragma unroll
        for (int w = 0; w < WARPS; w++) {
            float2 v = s_red[w][lane];
            sn += v.x; sd += v.y;
        }
        g_pnum[blockIdx.y * M + gpt] = sn;
        g_pden[blockIdx.y * M + gpt] = sd;
    }
}

// ---------------- D: per-row cubic interpolation + epilogue ----------------
__global__ void k_out(float* __restrict__ out, int n) {
    int i = blockIdx.x * blockDim.x + threadIdx.x;
    if (i >= n) return;
    float li = g_l[i];
    float u  = (li - g_lo) * g_invh;
    int cell = (int)u;
    cell = min(max(cell, 0), M - 2);
    float t = u - (float)cell;

    float p[4];
    #pragma unroll
    for (int k = 0; k < 4; k++) {
        int idx = min(max(cell + k - 1, 0), M - 1);
        float num = 0.f, den = 0.f;
        #pragma unroll
        for (int c = 0; c < KC; c++) {
            num += g_pnum[c * M + idx];
            den += g_pden[c * M + idx];
        }
        p[k] = __fdividef(num, den);
    }
    // Catmull-Rom
    float c0 = p[1];
    float c1 = 0.5f * (p[2] - p[0]);
    float c2 = p[0] - 2.5f * p[1] + 2.f * p[2] - 0.5f * p[3];
    float c3 = fmaf(1.5f, p[1] - p[2], 0.5f * (p[3] - p[0]));
    float a  = fmaf(fmaf(fmaf(c3, t, c2), t, c1), t, c0);

    float sn, cs;
    sincosf(a, &sn, &cs);
    ((float2*)out)[i] = make_float2(li * cs, li * sn);
}

extern "C" void kernel_launch(void* const* d_in, const int* in_sizes, int n_in,
                              void* d_out, int out_size) {
    const float* x = (const float*)d_in[0];
    float* out = (float*)d_out;
    int n = in_sizes[0] / 2;

    k_polar<<<(n + 255) / 256, 256>>>(x, n);
    k_statcompact<<<1, 1024>>>(n);
    dim3 grid(M / 32, KC);
    k_grid<<<grid, 32 * WARPS>>>();
    k_out<<<(n + 255) / 256, 256>>>(out, n);
}